// round 1
// baseline (speedup 1.0000x reference)
#include <cuda_runtime.h>
#include <math.h>

// ---------------- problem dims ----------------
constexpr int cB   = 2;
constexpr int cS   = 2048;
constexpr int cE   = 2048;
constexpr int cH   = 2688;
constexpr int cNH  = 4;
constexpr int cDH  = 672;   // cH / cNH
constexpr int cKS  = 4;
constexpr int cNPH = 672;   // cH / 4
constexpr long long cBS  = (long long)cB * cS;        // 4096
constexpr long long cBSH = cBS * cH;                  // 11,010,048
constexpr long long cSCORES = (long long)cB * cNH * cS * cS; // 33,554,432
constexpr int cBHS = cB * cNH * cS;                   // 16384

// ---------------- device scratch ----------------
__device__ float g_xm [cBSH];
__device__ float g_z  [cBSH];
__device__ float g_xca[cBSH];
__device__ float g_q  [cBSH];
__device__ float g_k  [cBSH];
__device__ float g_v  [cBSH];
__device__ float g_h  [cBSH];
__device__ float g_hs [cBSH];
__device__ float g_scores[cSCORES];
__device__ float g_ipre[cBHS];
__device__ float g_fpre[cBHS];
__device__ float g_cs  [cBHS];
__device__ float g_a   [cBHS];
__device__ float g_pm  [cBHS];
__device__ float g_rs  [cBHS];

// ---------------- generic tiled SGEMM ----------------
// C[M,N] = epilogue( alpha-modified A@B ), A row-major MxK, B either KxN (NN)
// or NxK (NT). Batched via blockIdx.z with two-level strides (z/nhd, z%nhd).
// mode 0: C = alpha * acc
// mode 1: scores epilogue: C = (n<=m) ? acc*alpha*exp(p1[n]-p2[m]) : 0   (causal, skip tiles above diag)
// mode 2: row scale:       C = acc * p1[m]; K-loop limited to tileM+BM (A causal lower-tri)
#define GBM 128
#define GBN 128
#define GBK 8

__global__ __launch_bounds__(256)
void sgemm_kernel(int M, int N, int K,
                  const float* __restrict__ A, int lda, long long sAb, long long sAn,
                  const float* __restrict__ B, int ldb, long long sBb, long long sBn,
                  float* __restrict__ C, int ldc, long long sCb, long long sCn,
                  int nhd, int transB, int mode, float alpha,
                  const float* __restrict__ p1, const float* __restrict__ p2, int pstr)
{
    int z  = blockIdx.z;
    int zb = z / nhd, zn = z % nhd;
    A += zb * sAb + zn * sAn;
    B += zb * sBb + zn * sBn;
    C += zb * sCb + zn * sCn;

    const int tileM = blockIdx.y * GBM;
    const int tileN = blockIdx.x * GBN;
    const int t = threadIdx.x;

    __shared__ float As[GBK][GBM];
    __shared__ float Bs[GBK][GBN];

    float acc[8][8];
#pragma unroll
    for (int i = 0; i < 8; i++)
#pragma unroll
        for (int j = 0; j < 8; j++) acc[i][j] = 0.f;

    const int tx = t & 15;        // 0..15 -> N
    const int ty = t >> 4;        // 0..15 -> M
    const int rowA  = t >> 1;     // 0..127
    const int colA4 = (t & 1) * 4;

    int Kend = K;
    if (mode == 2) { int lim = tileM + GBM; Kend = lim < K ? lim : K; }

    const bool skipTile = (mode == 1) && (tileN > tileM + GBM - 1);

    if (!skipTile) {
        for (int k0 = 0; k0 < Kend; k0 += GBK) {
            // ---- load A tile (transposed into smem) ----
            {
                int gm = tileM + rowA;
                float4 av = make_float4(0.f, 0.f, 0.f, 0.f);
                if (gm < M)
                    av = *reinterpret_cast<const float4*>(&A[(long long)gm * lda + k0 + colA4]);
                As[colA4 + 0][rowA] = av.x;
                As[colA4 + 1][rowA] = av.y;
                As[colA4 + 2][rowA] = av.z;
                As[colA4 + 3][rowA] = av.w;
            }
            // ---- load B tile ----
            if (!transB) {
                int kb  = t >> 5;            // 0..7
                int cn4 = (t & 31) * 4;      // 0..124
                int gn0 = tileN + cn4;
                const float* Brow = B + (long long)(k0 + kb) * ldb;
                float b0, b1, b2, b3;
                if (gn0 + 3 < N) {
                    float4 bv = *reinterpret_cast<const float4*>(Brow + gn0);
                    b0 = bv.x; b1 = bv.y; b2 = bv.z; b3 = bv.w;
                } else {
                    b0 = (gn0 + 0 < N) ? Brow[gn0 + 0] : 0.f;
                    b1 = (gn0 + 1 < N) ? Brow[gn0 + 1] : 0.f;
                    b2 = (gn0 + 2 < N) ? Brow[gn0 + 2] : 0.f;
                    b3 = (gn0 + 3 < N) ? Brow[gn0 + 3] : 0.f;
                }
                Bs[kb][cn4 + 0] = b0; Bs[kb][cn4 + 1] = b1;
                Bs[kb][cn4 + 2] = b2; Bs[kb][cn4 + 3] = b3;
            } else {
                int nb  = t >> 1;            // 0..127
                int kc4 = (t & 1) * 4;
                int gn  = tileN + nb;
                float4 bv = make_float4(0.f, 0.f, 0.f, 0.f);
                if (gn < N)
                    bv = *reinterpret_cast<const float4*>(&B[(long long)gn * ldb + k0 + kc4]);
                Bs[kc4 + 0][nb] = bv.x;
                Bs[kc4 + 1][nb] = bv.y;
                Bs[kc4 + 2][nb] = bv.z;
                Bs[kc4 + 3][nb] = bv.w;
            }
            __syncthreads();

#pragma unroll
            for (int kk = 0; kk < GBK; kk++) {
                float af[8], bf[8];
#pragma unroll
                for (int i = 0; i < 8; i++) af[i] = As[kk][ty * 8 + i];
#pragma unroll
                for (int j = 0; j < 8; j++) bf[j] = Bs[kk][tx * 8 + j];
#pragma unroll
                for (int i = 0; i < 8; i++)
#pragma unroll
                    for (int j = 0; j < 8; j++)
                        acc[i][j] += af[i] * bf[j];
            }
            __syncthreads();
        }
    }

    // ---- epilogue ----
#pragma unroll
    for (int i = 0; i < 8; i++) {
        int gm = tileM + ty * 8 + i;
        if (gm >= M) continue;
        float pmv = 0.f, rsv = 1.f;
        if (mode == 1) pmv = p2[(long long)z * pstr + gm];
        if (mode == 2) rsv = p1[(long long)z * pstr + gm];
        float* Crow = C + (long long)gm * ldc;
#pragma unroll
        for (int j = 0; j < 8; j++) {
            int gn = tileN + tx * 8 + j;
            if (gn >= N) continue;
            float v = acc[i][j];
            if (mode == 1) {
                v = (gn <= gm) ? v * alpha * expf(p1[(long long)z * pstr + gn] - pmv) : 0.f;
            } else if (mode == 2) {
                v = v * rsv;
            } else {
                v = v * alpha;
            }
            Crow[gn] = v;
        }
    }
}

// ---------------- depthwise causal conv + SiLU ----------------
__global__ void conv_silu_kernel(const float* __restrict__ xm,
                                 const float* __restrict__ w,
                                 const float* __restrict__ bias,
                                 float* __restrict__ xca)
{
    long long idx = (long long)blockIdx.x * blockDim.x + threadIdx.x;
    if (idx >= cBSH) return;
    int h = (int)(idx % cH);
    long long bs = idx / cH;
    int s = (int)(bs % cS);
    long long rowbase = (bs - s) * cH + h;
    float acc = bias[h];
#pragma unroll
    for (int tt = 0; tt < cKS; tt++) {
        int sp = s - (cKS - 1) + tt;
        if (sp >= 0) acc += xm[rowbase + (long long)sp * cH] * w[tt * cH + h];
    }
    float sg = 1.f / (1.f + expf(-acc));
    xca[idx] = acc * sg;
}

// ---------------- headwise 4x4 projections ----------------
__global__ void headwise_kernel(const float* __restrict__ xca,
                                const float* __restrict__ xm,
                                const float* __restrict__ Wq,
                                const float* __restrict__ Wk,
                                const float* __restrict__ Wv,
                                float* __restrict__ q,
                                float* __restrict__ k,
                                float* __restrict__ v)
{
    long long idx = (long long)blockIdx.x * blockDim.x + threadIdx.x;
    long long total = cBS * (long long)cNPH;
    if (idx >= total) return;
    int p = (int)(idx % cNPH);
    long long bs = idx / cNPH;
    long long base = bs * cH + p * 4;
    float4 xa = *reinterpret_cast<const float4*>(xca + base);
    float4 xv = *reinterpret_cast<const float4*>(xm + base);
    const float* wq = Wq + p * 16;
    const float* wk = Wk + p * 16;
    const float* wv = Wv + p * 16;
#pragma unroll
    for (int o = 0; o < 4; o++) {
        q[base + o] = xa.x * wq[o] + xa.y * wq[4 + o] + xa.z * wq[8 + o] + xa.w * wq[12 + o];
        k[base + o] = xa.x * wk[o] + xa.y * wk[4 + o] + xa.z * wk[8 + o] + xa.w * wk[12 + o];
        v[base + o] = xv.x * wv[o] + xv.y * wv[4 + o] + xv.z * wv[8 + o] + xv.w * wv[12 + o];
    }
}

// ---------------- gate projections (i_pre, f_pre) ----------------
__global__ __launch_bounds__(256)
void gates_kernel(const float* __restrict__ q, const float* __restrict__ k,
                  const float* __restrict__ v,
                  const float* __restrict__ Wig, const float* __restrict__ big,
                  const float* __restrict__ Wfg, const float* __restrict__ bfg,
                  float* __restrict__ ipre, float* __restrict__ fpre)
{
    int bs = blockIdx.x;     // 0..cBS-1
    int t  = threadIdx.x;
    long long base = (long long)bs * cH;
    float ai[4] = {0, 0, 0, 0}, af[4] = {0, 0, 0, 0};
    for (int r = t; r < 3 * cH; r += 256) {
        float val;
        if (r < cH)           val = q[base + r];
        else if (r < 2 * cH)  val = k[base + r - cH];
        else                  val = v[base + r - 2 * cH];
        float4 wi = *reinterpret_cast<const float4*>(Wig + (long long)r * 4);
        float4 wf = *reinterpret_cast<const float4*>(Wfg + (long long)r * 4);
        ai[0] += val * wi.x; ai[1] += val * wi.y; ai[2] += val * wi.z; ai[3] += val * wi.w;
        af[0] += val * wf.x; af[1] += val * wf.y; af[2] += val * wf.z; af[3] += val * wf.w;
    }
    __shared__ float red[8][256];
#pragma unroll
    for (int n = 0; n < 4; n++) { red[n][t] = ai[n]; red[4 + n][t] = af[n]; }
    __syncthreads();
    for (int o = 128; o > 0; o >>= 1) {
        if (t < o) {
#pragma unroll
            for (int m = 0; m < 8; m++) red[m][t] += red[m][t + o];
        }
        __syncthreads();
    }
    if (t == 0) {
        int b = bs / cS, s = bs % cS;
#pragma unroll
        for (int n = 0; n < 4; n++) {
            ipre[(long long)(b * cNH + n) * cS + s] = red[n][0] + big[n];
            fpre[(long long)(b * cNH + n) * cS + s] = red[4 + n][0] + bfg[n];
        }
    }
}

// ---------------- scan: cumsum(logsigmoid(f)), a = i - cs, prefix-max(a) ----------------
__global__ __launch_bounds__(256)
void scan_kernel(const float* __restrict__ ipre, const float* __restrict__ fpre,
                 float* __restrict__ cs, float* __restrict__ aArr, float* __restrict__ pm)
{
    int bh = blockIdx.x;
    int t  = threadIdx.x;
    const float* fp = fpre + (long long)bh * cS;
    const float* ip = ipre + (long long)bh * cS;

    float loc[8];
    float sum = 0.f;
#pragma unroll
    for (int u = 0; u < 8; u++) {
        int j = t * 8 + u;
        float f = fp[j];
        float lf = fminf(f, 0.f) - log1pf(expf(-fabsf(f)));
        sum += lf;
        loc[u] = sum;
    }
    __shared__ float part[256];
    part[t] = sum;
    __syncthreads();
    for (int off = 1; off < 256; off <<= 1) {
        float vv = (t >= off) ? part[t - off] : 0.f;
        __syncthreads();
        part[t] += vv;
        __syncthreads();
    }
    float excl = part[t] - sum;

    float av[8], lmax[8];
    float amax = -1e30f;
#pragma unroll
    for (int u = 0; u < 8; u++) {
        int j = t * 8 + u;
        float csj = excl + loc[u];
        cs[(long long)bh * cS + j] = csj;
        float aj = ip[j] - csj;
        aArr[(long long)bh * cS + j] = aj;
        av[u] = aj;
        amax = fmaxf(amax, aj);
        lmax[u] = amax;
    }
    __syncthreads();
    part[t] = amax;
    __syncthreads();
    for (int off = 1; off < 256; off <<= 1) {
        float vv = (t >= off) ? part[t - off] : -1e30f;
        __syncthreads();
        part[t] = fmaxf(part[t], vv);
        __syncthreads();
    }
    float exmax = (t > 0) ? part[t - 1] : -1e30f;
#pragma unroll
    for (int u = 0; u < 8; u++) {
        int j = t * 8 + u;
        (void)av;
        pm[(long long)bh * cS + j] = fmaxf(exmax, lmax[u]);
    }
}

// ---------------- per-row n and reciprocal scale rs ----------------
__global__ __launch_bounds__(256)
void nrs_kernel(const float* __restrict__ scores,
                const float* __restrict__ cs, const float* __restrict__ pm,
                float* __restrict__ rs)
{
    int i  = blockIdx.x;
    int bh = blockIdx.y;
    int t  = threadIdx.x;
    const float* row = scores + ((long long)bh * cS + i) * cS;
    float sum = 0.f;
    for (int j = t; j < cS; j += 256) sum += row[j];
    __shared__ float red[256];
    red[t] = sum;
    __syncthreads();
    for (int o = 128; o > 0; o >>= 1) {
        if (t < o) red[t] += red[t + o];
        __syncthreads();
    }
    if (t == 0) {
        float m = cs[(long long)bh * cS + i] + pm[(long long)bh * cS + i];
        float n = fmaxf(fabsf(red[0]), expf(-m));
        rs[(long long)bh * cS + i] = 1.f / (n + 1e-6f);
    }
}

// ---------------- multi-head LN + skip + z-gate ----------------
__global__ __launch_bounds__(256)
void ln_kernel(const float* __restrict__ hbuf, const float* __restrict__ xca,
               const float* __restrict__ zbuf, const float* __restrict__ norm_w,
               const float* __restrict__ skip, float* __restrict__ hs)
{
    int s  = blockIdx.x;
    int bh = blockIdx.y;
    int t  = threadIdx.x;
    int b = bh / cNH, n = bh % cNH;
    const float* hrow = hbuf + ((long long)bh * cS + s) * cDH;

    float sum = 0.f, ss = 0.f;
    for (int d = t; d < cDH; d += 256) {
        float v = hrow[d];
        sum += v; ss += v * v;
    }
    __shared__ float r1[256], r2[256];
    r1[t] = sum; r2[t] = ss;
    __syncthreads();
    for (int o = 128; o > 0; o >>= 1) {
        if (t < o) { r1[t] += r1[t + o]; r2[t] += r2[t + o]; }
        __syncthreads();
    }
    float mean = r1[0] / cDH;
    float var  = r2[0] / cDH - mean * mean;
    float inv  = rsqrtf(var + 1e-5f);

    long long xbase = ((long long)b * cS + s) * cH;
    for (int d = t; d < cDH; d += 256) {
        int col = n * cDH + d;
        float hn = (hrow[d] - mean) * inv * norm_w[col];
        float hk = hn + skip[col] * xca[xbase + col];
        float zv = zbuf[xbase + col];
        float sz = zv / (1.f + expf(-zv));
        hs[xbase + col] = hk * sz;
    }
}

// ---------------- launch ----------------
extern "C" void kernel_launch(void* const* d_in, const int* in_sizes, int n_in,
                              void* d_out, int out_size)
{
    const float* x      = (const float*)d_in[0];
    const float* W_in   = (const float*)d_in[1];
    const float* conv_w = (const float*)d_in[2];
    const float* conv_b = (const float*)d_in[3];
    const float* Wq     = (const float*)d_in[4];
    const float* Wk     = (const float*)d_in[5];
    const float* Wv     = (const float*)d_in[6];
    const float* W_ig   = (const float*)d_in[7];
    const float* b_ig   = (const float*)d_in[8];
    const float* W_fg   = (const float*)d_in[9];
    const float* b_fg   = (const float*)d_in[10];
    const float* norm_w = (const float*)d_in[11];
    const float* skip   = (const float*)d_in[12];
    const float* W_out  = (const float*)d_in[13];
    float* out = (float*)d_out;

    float *p_xm, *p_z, *p_xca, *p_q, *p_k, *p_v, *p_h, *p_hs, *p_sc;
    float *p_ipre, *p_fpre, *p_cs, *p_a, *p_pm, *p_rs;
    cudaGetSymbolAddress((void**)&p_xm,  g_xm);
    cudaGetSymbolAddress((void**)&p_z,   g_z);
    cudaGetSymbolAddress((void**)&p_xca, g_xca);
    cudaGetSymbolAddress((void**)&p_q,   g_q);
    cudaGetSymbolAddress((void**)&p_k,   g_k);
    cudaGetSymbolAddress((void**)&p_v,   g_v);
    cudaGetSymbolAddress((void**)&p_h,   g_h);
    cudaGetSymbolAddress((void**)&p_hs,  g_hs);
    cudaGetSymbolAddress((void**)&p_sc,  g_scores);
    cudaGetSymbolAddress((void**)&p_ipre, g_ipre);
    cudaGetSymbolAddress((void**)&p_fpre, g_fpre);
    cudaGetSymbolAddress((void**)&p_cs,  g_cs);
    cudaGetSymbolAddress((void**)&p_a,   g_a);
    cudaGetSymbolAddress((void**)&p_pm,  g_pm);
    cudaGetSymbolAddress((void**)&p_rs,  g_rs);

    const int M0 = (int)cBS;  // 4096

    // 1) x @ W_in[:, :H] -> xm ; x @ W_in[:, H:] -> z
    {
        dim3 grid(cH / GBN, M0 / GBM, 1);
        sgemm_kernel<<<grid, 256>>>(M0, cH, cE,
            x, cE, 0, 0,
            W_in, 2 * cH, 0, 0,
            p_xm, cH, 0, 0,
            1, 0, 0, 1.0f, nullptr, nullptr, 0);
        sgemm_kernel<<<grid, 256>>>(M0, cH, cE,
            x, cE, 0, 0,
            W_in + cH, 2 * cH, 0, 0,
            p_z, cH, 0, 0,
            1, 0, 0, 1.0f, nullptr, nullptr, 0);
    }

    // 2) depthwise causal conv + SiLU
    {
        long long total = cBSH;
        int blocks = (int)((total + 255) / 256);
        conv_silu_kernel<<<blocks, 256>>>(p_xm, conv_w, conv_b, p_xca);
    }

    // 3) headwise q/k/v
    {
        long long total = cBS * (long long)cNPH;
        int blocks = (int)((total + 255) / 256);
        headwise_kernel<<<blocks, 256>>>(p_xca, p_xm, Wq, Wk, Wv, p_q, p_k, p_v);
    }

    // 4) gates
    gates_kernel<<<M0, 256>>>(p_q, p_k, p_v, W_ig, b_ig, W_fg, b_fg, p_ipre, p_fpre);

    // 5) scan
    scan_kernel<<<cB * cNH, 256>>>(p_ipre, p_fpre, p_cs, p_a, p_pm);

    // 6) scores = (q k^T / sqrt(DH)) * exp(a_j - pm_i), causal (batched over 8 heads)
    {
        dim3 grid(cS / GBN, cS / GBM, cB * cNH);
        float alpha = 1.0f / sqrtf((float)cDH);
        sgemm_kernel<<<grid, 256>>>(cS, cS, cDH,
            p_q, cH, (long long)cS * cH, (long long)cDH,
            p_k, cH, (long long)cS * cH, (long long)cDH,
            p_sc, cS, (long long)cNH * cS * cS, (long long)cS * cS,
            cNH, 1, 1, alpha, p_a, p_pm, cS);
    }

    // 7) row sums -> n -> rs
    {
        dim3 grid(cS, cB * cNH);
        nrs_kernel<<<grid, 256>>>(p_sc, p_cs, p_pm, p_rs);
    }

    // 8) h = diag(rs) * scores @ v   (causal K-limit)
    {
        dim3 grid((cDH + GBN - 1) / GBN, cS / GBM, cB * cNH);
        sgemm_kernel<<<grid, 256>>>(cS, cDH, cS,
            p_sc, cS, (long long)cNH * cS * cS, (long long)cS * cS,
            p_v, cH, (long long)cS * cH, (long long)cDH,
            p_h, cDH, (long long)cNH * cS * cDH, (long long)cS * cDH,
            cNH, 0, 2, 1.0f, p_rs, nullptr, cS);
    }

    // 9) LN + skip + z gate
    {
        dim3 grid(cS, cB * cNH);
        ln_kernel<<<grid, 256>>>(p_h, p_xca, p_z, norm_w, skip, p_hs);
    }

    // 10) out = hs @ W_out
    {
        dim3 grid(cE / GBN, M0 / GBM, 1);
        sgemm_kernel<<<grid, 256>>>(M0, cE, cH,
            p_hs, cH, 0, 0,
            W_out, cE, 0, 0,
            out, cE, 0, 0,
            1, 0, 0, 1.0f, nullptr, nullptr, 0);
    }
}

// round 2
// speedup vs baseline: 2.2861x; 2.2861x over previous
#include <cuda_runtime.h>
#include <math.h>
#include <stdint.h>

// ---------------- problem dims ----------------
constexpr int cB   = 2;
constexpr int cS   = 2048;
constexpr int cE   = 2048;
constexpr int cH   = 2688;
constexpr int cNH  = 4;
constexpr int cDH  = 672;   // cH / cNH
constexpr int cKS  = 4;
constexpr int cNPH = 672;   // cH / 4
constexpr long long cBS  = (long long)cB * cS;        // 4096
constexpr long long cBSH = cBS * cH;                  // 11,010,048
constexpr long long cSCORES = (long long)cB * cNH * cS * cS; // 33,554,432
constexpr int cBHS = cB * cNH * cS;                   // 16384

// ---------------- device scratch ----------------
__device__ float g_xm [cBSH];
__device__ float g_z  [cBSH];
__device__ float g_xca[cBSH];
__device__ float g_q  [cBSH];
__device__ float g_k  [cBSH];
__device__ float g_v  [cBSH];
__device__ float g_h  [cBSH];
__device__ float g_hs [cBSH];
__device__ float g_scores[cSCORES];
__device__ float g_ipre[cBHS];
__device__ float g_fpre[cBHS];
__device__ float g_cs  [cBHS];
__device__ float g_a   [cBHS];
__device__ float g_pm  [cBHS];
__device__ float g_rs  [cBHS];

// ---------------- tf32 helpers ----------------
__device__ __forceinline__ uint32_t f2tf32(float x) {
    uint32_t r;
    asm("cvt.rna.tf32.f32 %0, %1;" : "=r"(r) : "f"(x));
    return r;
}

#define MMA_TF32(d, a, b)                                                      \
    asm volatile(                                                              \
        "mma.sync.aligned.m16n8k8.row.col.f32.tf32.tf32.f32 "                  \
        "{%0,%1,%2,%3},{%4,%5,%6,%7},{%8,%9},{%0,%1,%2,%3};\n"                 \
        : "+f"(d[0]), "+f"(d[1]), "+f"(d[2]), "+f"(d[3])                       \
        : "r"(a[0]), "r"(a[1]), "r"(a[2]), "r"(a[3]), "r"(b[0]), "r"(b[1]))

// ---------------- tf32 tensor-core GEMM ----------------
// C[M,N] = epilogue(A@B). A row-major MxK. B: KxN (transB=0) or NxK (transB=1).
// Batched via blockIdx.z with two-level strides. M%128==0, K%16==0 assumed.
// mode 0: C = alpha * acc
// mode 1: scores: C = (n<=m) ? acc*alpha*exp(p1[n]-p2[m]) : 0 ; tiles fully
//         above the diagonal are skipped entirely (no writes).
// mode 2: row scale: C = acc * p1[m]; K limited to tileM+128 (A lower-tri).
#define BM 128
#define BN 128
#define BK 16

__global__ __launch_bounds__(256)
void tgemm_kernel(int M, int N, int K,
                  const float* __restrict__ A, int lda, long long sAb, long long sAn,
                  const float* __restrict__ B, int ldb, long long sBb, long long sBn,
                  float* __restrict__ C, int ldc, long long sCb, long long sCn,
                  int nhd, int transB, int mode, float alpha,
                  const float* __restrict__ p1, const float* __restrict__ p2, int pstr)
{
    const int z  = blockIdx.z;
    const int zb = z / nhd, zn = z % nhd;
    A += zb * sAb + zn * sAn;
    B += zb * sBb + zn * sBn;
    C += zb * sCb + zn * sCn;

    const int tileM = blockIdx.y * BM;
    const int tileN = blockIdx.x * BN;
    if (mode == 1 && tileN > tileM + BM - 1) return;   // fully masked tile

    const int t    = threadIdx.x;
    const int lane = t & 31;
    const int warp = t >> 5;
    const int g    = lane >> 2;     // 0..7
    const int t4   = lane & 3;      // 0..3
    const int wm   = (warp & 1) * 64;
    const int wn   = (warp >> 1) * 32;

    __shared__ float As[BK][BM + 4];
    __shared__ float Bs[BK][BN + 4];

    float acc[4][4][4];
#pragma unroll
    for (int i = 0; i < 4; i++)
#pragma unroll
        for (int j = 0; j < 4; j++)
#pragma unroll
            for (int r = 0; r < 4; r++) acc[i][j][r] = 0.f;

    int Kend = K;
    if (mode == 2) { int lim = tileM + BM; Kend = lim < K ? lim : K; }

    // load-thread mapping
    const int rowA = t >> 1;           // 0..127
    const int colA = (t & 1) * 8;      // 0 or 8
    const int kb   = t >> 4;           // 0..15  (NN B)
    const int cn   = (t & 15) * 8;     // 0..120 (NN B)
    const int nb   = t >> 1;           // 0..127 (NT B)
    const int kc   = (t & 1) * 8;      // 0 or 8 (NT B)

    float ar[8], br[8];

    // ---- prefetch k0 = 0 ----
    {
        const float4* pa = reinterpret_cast<const float4*>(
            &A[(long long)(tileM + rowA) * lda + colA]);
        float4 a0 = pa[0], a1 = pa[1];
        ar[0]=a0.x; ar[1]=a0.y; ar[2]=a0.z; ar[3]=a0.w;
        ar[4]=a1.x; ar[5]=a1.y; ar[6]=a1.z; ar[7]=a1.w;
        if (!transB) {
            int gn0 = tileN + cn;
            const float* Brow = B + (long long)kb * ldb;
            if (gn0 + 7 < N) {
                float4 b0 = *reinterpret_cast<const float4*>(Brow + gn0);
                float4 b1 = *reinterpret_cast<const float4*>(Brow + gn0 + 4);
                br[0]=b0.x; br[1]=b0.y; br[2]=b0.z; br[3]=b0.w;
                br[4]=b1.x; br[5]=b1.y; br[6]=b1.z; br[7]=b1.w;
            } else {
#pragma unroll
                for (int u = 0; u < 8; u++) br[u] = (gn0 + u < N) ? Brow[gn0 + u] : 0.f;
            }
        } else {
            const float4* pb = reinterpret_cast<const float4*>(
                &B[(long long)(tileN + nb) * ldb + kc]);
            float4 b0 = pb[0], b1 = pb[1];
            br[0]=b0.x; br[1]=b0.y; br[2]=b0.z; br[3]=b0.w;
            br[4]=b1.x; br[5]=b1.y; br[6]=b1.z; br[7]=b1.w;
        }
    }

    for (int k0 = 0; k0 < Kend; k0 += BK) {
        // ---- regs -> smem (convert to tf32) ----
#pragma unroll
        for (int u = 0; u < 8; u++)
            As[colA + u][rowA] = __uint_as_float(f2tf32(ar[u]));
        if (!transB) {
#pragma unroll
            for (int u = 0; u < 8; u++)
                Bs[kb][cn + u] = __uint_as_float(f2tf32(br[u]));
        } else {
#pragma unroll
            for (int u = 0; u < 8; u++)
                Bs[kc + u][nb] = __uint_as_float(f2tf32(br[u]));
        }
        __syncthreads();

        // ---- prefetch next iter ----
        int kn = k0 + BK;
        if (kn < Kend) {
            const float4* pa = reinterpret_cast<const float4*>(
                &A[(long long)(tileM + rowA) * lda + kn + colA]);
            float4 a0 = pa[0], a1 = pa[1];
            ar[0]=a0.x; ar[1]=a0.y; ar[2]=a0.z; ar[3]=a0.w;
            ar[4]=a1.x; ar[5]=a1.y; ar[6]=a1.z; ar[7]=a1.w;
            if (!transB) {
                int gn0 = tileN + cn;
                const float* Brow = B + (long long)(kn + kb) * ldb;
                if (gn0 + 7 < N) {
                    float4 b0 = *reinterpret_cast<const float4*>(Brow + gn0);
                    float4 b1 = *reinterpret_cast<const float4*>(Brow + gn0 + 4);
                    br[0]=b0.x; br[1]=b0.y; br[2]=b0.z; br[3]=b0.w;
                    br[4]=b1.x; br[5]=b1.y; br[6]=b1.z; br[7]=b1.w;
                } else {
#pragma unroll
                    for (int u = 0; u < 8; u++) br[u] = (gn0 + u < N) ? Brow[gn0 + u] : 0.f;
                }
            } else {
                const float4* pb = reinterpret_cast<const float4*>(
                    &B[(long long)(tileN + nb) * ldb + kn + kc]);
                float4 b0 = pb[0], b1 = pb[1];
                br[0]=b0.x; br[1]=b0.y; br[2]=b0.z; br[3]=b0.w;
                br[4]=b1.x; br[5]=b1.y; br[6]=b1.z; br[7]=b1.w;
            }
        }

        // ---- compute BK=16 (two k=8 mma steps) ----
#pragma unroll
        for (int ks = 0; ks < BK; ks += 8) {
            uint32_t af[4][4], bf[4][2];
#pragma unroll
            for (int i = 0; i < 4; i++) {
                int m0 = wm + i * 16 + g;
                af[i][0] = __float_as_uint(As[ks + t4    ][m0    ]);
                af[i][1] = __float_as_uint(As[ks + t4    ][m0 + 8]);
                af[i][2] = __float_as_uint(As[ks + t4 + 4][m0    ]);
                af[i][3] = __float_as_uint(As[ks + t4 + 4][m0 + 8]);
            }
#pragma unroll
            for (int j = 0; j < 4; j++) {
                int n0 = wn + j * 8 + g;
                bf[j][0] = __float_as_uint(Bs[ks + t4    ][n0]);
                bf[j][1] = __float_as_uint(Bs[ks + t4 + 4][n0]);
            }
#pragma unroll
            for (int i = 0; i < 4; i++)
#pragma unroll
                for (int j = 0; j < 4; j++)
                    MMA_TF32(acc[i][j], af[i], bf[j]);
        }
        __syncthreads();
    }

    // ---- epilogue ----
    const long long zoff = (long long)z * pstr;
#pragma unroll
    for (int i = 0; i < 4; i++) {
        int gmBase = tileM + wm + i * 16 + g;
#pragma unroll
        for (int half = 0; half < 2; half++) {
            int gm = gmBase + half * 8;
            float pmv = 0.f, rsv = 1.f;
            if (mode == 1)      pmv = p2[zoff + gm];
            else if (mode == 2) rsv = p1[zoff + gm];
            float* Crow = C + (long long)gm * ldc;
#pragma unroll
            for (int j = 0; j < 4; j++) {
                int gn = tileN + wn + j * 8 + t4 * 2;
                if (gn >= N) continue;
                float v0 = acc[i][j][half * 2 + 0];
                float v1 = acc[i][j][half * 2 + 1];
                if (mode == 1) {
                    v0 = (gn     <= gm) ? v0 * alpha * __expf(p1[zoff + gn    ] - pmv) : 0.f;
                    v1 = (gn + 1 <= gm) ? v1 * alpha * __expf(p1[zoff + gn + 1] - pmv) : 0.f;
                } else if (mode == 2) {
                    v0 *= rsv; v1 *= rsv;
                } else {
                    v0 *= alpha; v1 *= alpha;
                }
                *reinterpret_cast<float2*>(&Crow[gn]) = make_float2(v0, v1);
            }
        }
    }
}

// ---------------- depthwise causal conv + SiLU ----------------
__global__ void conv_silu_kernel(const float* __restrict__ xm,
                                 const float* __restrict__ w,
                                 const float* __restrict__ bias,
                                 float* __restrict__ xca)
{
    long long idx = (long long)blockIdx.x * blockDim.x + threadIdx.x;
    if (idx >= cBSH) return;
    int h = (int)(idx % cH);
    long long bs = idx / cH;
    int s = (int)(bs % cS);
    long long rowbase = (bs - s) * cH + h;
    float acc = bias[h];
#pragma unroll
    for (int tt = 0; tt < cKS; tt++) {
        int sp = s - (cKS - 1) + tt;
        if (sp >= 0) acc += xm[rowbase + (long long)sp * cH] * w[tt * cH + h];
    }
    float sg = 1.f / (1.f + __expf(-acc));
    xca[idx] = acc * sg;
}

// ---------------- headwise 4x4 projections (vectorized) ----------------
__global__ void headwise_kernel(const float* __restrict__ xca,
                                const float* __restrict__ xm,
                                const float* __restrict__ Wq,
                                const float* __restrict__ Wk,
                                const float* __restrict__ Wv,
                                float* __restrict__ q,
                                float* __restrict__ k,
                                float* __restrict__ v)
{
    long long idx = (long long)blockIdx.x * blockDim.x + threadIdx.x;
    long long total = cBS * (long long)cNPH;
    if (idx >= total) return;
    int p = (int)(idx % cNPH);
    long long bs = idx / cNPH;
    long long base = bs * cH + p * 4;
    float4 xa = *reinterpret_cast<const float4*>(xca + base);
    float4 xv = *reinterpret_cast<const float4*>(xm + base);
    const float* wq = Wq + p * 16;
    const float* wk = Wk + p * 16;
    const float* wv = Wv + p * 16;
    float qo[4], ko[4], vo[4];
#pragma unroll
    for (int o = 0; o < 4; o++) {
        qo[o] = xa.x * wq[o] + xa.y * wq[4 + o] + xa.z * wq[8 + o] + xa.w * wq[12 + o];
        ko[o] = xa.x * wk[o] + xa.y * wk[4 + o] + xa.z * wk[8 + o] + xa.w * wk[12 + o];
        vo[o] = xv.x * wv[o] + xv.y * wv[4 + o] + xv.z * wv[8 + o] + xv.w * wv[12 + o];
    }
    *reinterpret_cast<float4*>(q + base) = make_float4(qo[0], qo[1], qo[2], qo[3]);
    *reinterpret_cast<float4*>(k + base) = make_float4(ko[0], ko[1], ko[2], ko[3]);
    *reinterpret_cast<float4*>(v + base) = make_float4(vo[0], vo[1], vo[2], vo[3]);
}

// ---------------- gate projections (i_pre, f_pre) ----------------
__global__ __launch_bounds__(256)
void gates_kernel(const float* __restrict__ q, const float* __restrict__ k,
                  const float* __restrict__ v,
                  const float* __restrict__ Wig, const float* __restrict__ big,
                  const float* __restrict__ Wfg, const float* __restrict__ bfg,
                  float* __restrict__ ipre, float* __restrict__ fpre)
{
    int bs = blockIdx.x;     // 0..cBS-1
    int t  = threadIdx.x;
    long long base = (long long)bs * cH;
    float ai[4] = {0, 0, 0, 0}, af[4] = {0, 0, 0, 0};
    for (int r = t; r < 3 * cH; r += 256) {
        float val;
        if (r < cH)           val = q[base + r];
        else if (r < 2 * cH)  val = k[base + r - cH];
        else                  val = v[base + r - 2 * cH];
        float4 wi = *reinterpret_cast<const float4*>(Wig + (long long)r * 4);
        float4 wf = *reinterpret_cast<const float4*>(Wfg + (long long)r * 4);
        ai[0] += val * wi.x; ai[1] += val * wi.y; ai[2] += val * wi.z; ai[3] += val * wi.w;
        af[0] += val * wf.x; af[1] += val * wf.y; af[2] += val * wf.z; af[3] += val * wf.w;
    }
    __shared__ float red[8][256];
#pragma unroll
    for (int n = 0; n < 4; n++) { red[n][t] = ai[n]; red[4 + n][t] = af[n]; }
    __syncthreads();
    for (int o = 128; o > 0; o >>= 1) {
        if (t < o) {
#pragma unroll
            for (int m = 0; m < 8; m++) red[m][t] += red[m][t + o];
        }
        __syncthreads();
    }
    if (t == 0) {
        int b = bs / cS, s = bs % cS;
#pragma unroll
        for (int n = 0; n < 4; n++) {
            ipre[(long long)(b * cNH + n) * cS + s] = red[n][0] + big[n];
            fpre[(long long)(b * cNH + n) * cS + s] = red[4 + n][0] + bfg[n];
        }
    }
}

// ---------------- scan: cumsum(logsigmoid(f)), a = i - cs, prefix-max(a) ----------------
__global__ __launch_bounds__(256)
void scan_kernel(const float* __restrict__ ipre, const float* __restrict__ fpre,
                 float* __restrict__ cs, float* __restrict__ aArr, float* __restrict__ pm)
{
    int bh = blockIdx.x;
    int t  = threadIdx.x;
    const float* fp = fpre + (long long)bh * cS;
    const float* ip = ipre + (long long)bh * cS;

    float loc[8];
    float sum = 0.f;
#pragma unroll
    for (int u = 0; u < 8; u++) {
        int j = t * 8 + u;
        float f = fp[j];
        float lf = fminf(f, 0.f) - log1pf(expf(-fabsf(f)));
        sum += lf;
        loc[u] = sum;
    }
    __shared__ float part[256];
    part[t] = sum;
    __syncthreads();
    for (int off = 1; off < 256; off <<= 1) {
        float vv = (t >= off) ? part[t - off] : 0.f;
        __syncthreads();
        part[t] += vv;
        __syncthreads();
    }
    float excl = part[t] - sum;

    float lmax[8];
    float amax = -1e30f;
#pragma unroll
    for (int u = 0; u < 8; u++) {
        int j = t * 8 + u;
        float csj = excl + loc[u];
        cs[(long long)bh * cS + j] = csj;
        float aj = ip[j] - csj;
        aArr[(long long)bh * cS + j] = aj;
        amax = fmaxf(amax, aj);
        lmax[u] = amax;
    }
    __syncthreads();
    part[t] = amax;
    __syncthreads();
    for (int off = 1; off < 256; off <<= 1) {
        float vv = (t >= off) ? part[t - off] : -1e30f;
        __syncthreads();
        part[t] = fmaxf(part[t], vv);
        __syncthreads();
    }
    float exmax = (t > 0) ? part[t - 1] : -1e30f;
#pragma unroll
    for (int u = 0; u < 8; u++) {
        int j = t * 8 + u;
        pm[(long long)bh * cS + j] = fmaxf(exmax, lmax[u]);
    }
}

// ---------------- per-row n and reciprocal scale rs (causal sum) ----------------
__global__ __launch_bounds__(256)
void nrs_kernel(const float* __restrict__ scores,
                const float* __restrict__ cs, const float* __restrict__ pm,
                float* __restrict__ rs)
{
    int i  = blockIdx.x;
    int bh = blockIdx.y;
    int t  = threadIdx.x;
    const float* row = scores + ((long long)bh * cS + i) * cS;
    float sum = 0.f;
    for (int j = t; j <= i; j += 256) sum += row[j];
    __shared__ float red[256];
    red[t] = sum;
    __syncthreads();
    for (int o = 128; o > 0; o >>= 1) {
        if (t < o) red[t] += red[t + o];
        __syncthreads();
    }
    if (t == 0) {
        float m = cs[(long long)bh * cS + i] + pm[(long long)bh * cS + i];
        float n = fmaxf(fabsf(red[0]), __expf(-m));
        rs[(long long)bh * cS + i] = 1.f / (n + 1e-6f);
    }
}

// ---------------- multi-head LN + skip + z-gate ----------------
__global__ __launch_bounds__(256)
void ln_kernel(const float* __restrict__ hbuf, const float* __restrict__ xca,
               const float* __restrict__ zbuf, const float* __restrict__ norm_w,
               const float* __restrict__ skip, float* __restrict__ hs)
{
    int s  = blockIdx.x;
    int bh = blockIdx.y;
    int t  = threadIdx.x;
    int b = bh / cNH, n = bh % cNH;
    const float* hrow = hbuf + ((long long)bh * cS + s) * cDH;

    float sum = 0.f, ss = 0.f;
    for (int d = t; d < cDH; d += 256) {
        float v = hrow[d];
        sum += v; ss += v * v;
    }
    __shared__ float r1[256], r2[256];
    r1[t] = sum; r2[t] = ss;
    __syncthreads();
    for (int o = 128; o > 0; o >>= 1) {
        if (t < o) { r1[t] += r1[t + o]; r2[t] += r2[t + o]; }
        __syncthreads();
    }
    float mean = r1[0] / cDH;
    float var  = r2[0] / cDH - mean * mean;
    float inv  = rsqrtf(var + 1e-5f);

    long long xbase = ((long long)b * cS + s) * cH;
    for (int d = t; d < cDH; d += 256) {
        int col = n * cDH + d;
        float hn = (hrow[d] - mean) * inv * norm_w[col];
        float hk = hn + skip[col] * xca[xbase + col];
        float zv = zbuf[xbase + col];
        float sz = zv / (1.f + __expf(-zv));
        hs[xbase + col] = hk * sz;
    }
}

// ---------------- launch ----------------
extern "C" void kernel_launch(void* const* d_in, const int* in_sizes, int n_in,
                              void* d_out, int out_size)
{
    const float* x      = (const float*)d_in[0];
    const float* W_in   = (const float*)d_in[1];
    const float* conv_w = (const float*)d_in[2];
    const float* conv_b = (const float*)d_in[3];
    const float* Wq     = (const float*)d_in[4];
    const float* Wk     = (const float*)d_in[5];
    const float* Wv     = (const float*)d_in[6];
    const float* W_ig   = (const float*)d_in[7];
    const float* b_ig   = (const float*)d_in[8];
    const float* W_fg   = (const float*)d_in[9];
    const float* b_fg   = (const float*)d_in[10];
    const float* norm_w = (const float*)d_in[11];
    const float* skip   = (const float*)d_in[12];
    const float* W_out  = (const float*)d_in[13];
    float* out = (float*)d_out;

    float *p_xm, *p_z, *p_xca, *p_q, *p_k, *p_v, *p_h, *p_hs, *p_sc;
    float *p_ipre, *p_fpre, *p_cs, *p_a, *p_pm, *p_rs;
    cudaGetSymbolAddress((void**)&p_xm,  g_xm);
    cudaGetSymbolAddress((void**)&p_z,   g_z);
    cudaGetSymbolAddress((void**)&p_xca, g_xca);
    cudaGetSymbolAddress((void**)&p_q,   g_q);
    cudaGetSymbolAddress((void**)&p_k,   g_k);
    cudaGetSymbolAddress((void**)&p_v,   g_v);
    cudaGetSymbolAddress((void**)&p_h,   g_h);
    cudaGetSymbolAddress((void**)&p_hs,  g_hs);
    cudaGetSymbolAddress((void**)&p_sc,  g_scores);
    cudaGetSymbolAddress((void**)&p_ipre, g_ipre);
    cudaGetSymbolAddress((void**)&p_fpre, g_fpre);
    cudaGetSymbolAddress((void**)&p_cs,  g_cs);
    cudaGetSymbolAddress((void**)&p_a,   g_a);
    cudaGetSymbolAddress((void**)&p_pm,  g_pm);
    cudaGetSymbolAddress((void**)&p_rs,  g_rs);

    const int M0 = (int)cBS;  // 4096

    // 1) x @ W_in[:, :H] -> xm ; x @ W_in[:, H:] -> z
    {
        dim3 grid(cH / BN, M0 / BM, 1);
        tgemm_kernel<<<grid, 256>>>(M0, cH, cE,
            x, cE, 0, 0,
            W_in, 2 * cH, 0, 0,
            p_xm, cH, 0, 0,
            1, 0, 0, 1.0f, nullptr, nullptr, 0);
        tgemm_kernel<<<grid, 256>>>(M0, cH, cE,
            x, cE, 0, 0,
            W_in + cH, 2 * cH, 0, 0,
            p_z, cH, 0, 0,
            1, 0, 0, 1.0f, nullptr, nullptr, 0);
    }

    // 2) depthwise causal conv + SiLU
    {
        long long total = cBSH;
        int blocks = (int)((total + 255) / 256);
        conv_silu_kernel<<<blocks, 256>>>(p_xm, conv_w, conv_b, p_xca);
    }

    // 3) headwise q/k/v
    {
        long long total = cBS * (long long)cNPH;
        int blocks = (int)((total + 255) / 256);
        headwise_kernel<<<blocks, 256>>>(p_xca, p_xm, Wq, Wk, Wv, p_q, p_k, p_v);
    }

    // 4) gates
    gates_kernel<<<M0, 256>>>(p_q, p_k, p_v, W_ig, b_ig, W_fg, b_fg, p_ipre, p_fpre);

    // 5) scan
    scan_kernel<<<cB * cNH, 256>>>(p_ipre, p_fpre, p_cs, p_a, p_pm);

    // 6) scores = (q k^T / sqrt(DH)) * exp(a_j - pm_i), causal (batched over 8 heads)
    {
        dim3 grid(cS / BN, cS / BM, cB * cNH);
        float alpha = 1.0f / sqrtf((float)cDH);
        tgemm_kernel<<<grid, 256>>>(cS, cS, cDH,
            p_q, cH, (long long)cS * cH, (long long)cDH,
            p_k, cH, (long long)cS * cH, (long long)cDH,
            p_sc, cS, (long long)cNH * cS * cS, (long long)cS * cS,
            cNH, 1, 1, alpha, p_a, p_pm, cS);
    }

    // 7) row sums -> n -> rs
    {
        dim3 grid(cS, cB * cNH);
        nrs_kernel<<<grid, 256>>>(p_sc, p_cs, p_pm, p_rs);
    }

    // 8) h = diag(rs) * scores @ v   (causal K-limit)
    {
        dim3 grid((cDH + BN - 1) / BN, cS / BM, cB * cNH);
        tgemm_kernel<<<grid, 256>>>(cS, cDH, cS,
            p_sc, cS, (long long)cNH * cS * cS, (long long)cS * cS,
            p_v, cH, (long long)cS * cH, (long long)cDH,
            p_h, cDH, (long long)cNH * cS * cDH, (long long)cS * cDH,
            cNH, 0, 2, 1.0f, p_rs, nullptr, cS);
    }

    // 9) LN + skip + z gate
    {
        dim3 grid(cS, cB * cNH);
        ln_kernel<<<grid, 256>>>(p_h, p_xca, p_z, norm_w, skip, p_hs);
    }

    // 10) out = hs @ W_out
    {
        dim3 grid(cE / BN, M0 / BM, 1);
        tgemm_kernel<<<grid, 256>>>(M0, cE, cH,
            p_hs, cH, 0, 0,
            W_out, cE, 0, 0,
            out, cE, 0, 0,
            1, 0, 0, 1.0f, nullptr, nullptr, 0);
    }
}

// round 3
// speedup vs baseline: 3.2344x; 1.4148x over previous
#include <cuda_runtime.h>
#include <math.h>
#include <stdint.h>

// ---------------- problem dims ----------------
constexpr int cB   = 2;
constexpr int cS   = 2048;
constexpr int cE   = 2048;
constexpr int cH   = 2688;
constexpr int cNH  = 4;
constexpr int cDH  = 672;   // cH / cNH
constexpr int cKS  = 4;
constexpr int cNPH = 672;   // cH / 4
constexpr long long cBS  = (long long)cB * cS;        // 4096
constexpr long long cBSH = cBS * cH;                  // 11,010,048
constexpr long long cSCORES = (long long)cB * cNH * cS * cS; // 33,554,432
constexpr int cBHS = cB * cNH * cS;                   // 16384

// ---------------- device scratch ----------------
__device__ float g_xm [cBSH];
__device__ float g_z  [cBSH];
__device__ float g_xca[cBSH];
__device__ float g_q  [cBSH];
__device__ float g_k  [cBSH];
__device__ float g_v  [cBSH];
__device__ float g_h  [cBSH];
__device__ float g_hs [cBSH];
__device__ float g_scores[cSCORES];
__device__ float g_ipre[cBHS];
__device__ float g_fpre[cBHS];
__device__ float g_cs  [cBHS];
__device__ float g_a   [cBHS];
__device__ float g_pm  [cBHS];
__device__ float g_rs  [cBHS];
__device__ float g_nsum[cBHS];

// ---------------- helpers ----------------
__device__ __forceinline__ uint32_t f2tf32(float x) {
    uint32_t r;
    asm("cvt.rna.tf32.f32 %0, %1;" : "=r"(r) : "f"(x));
    return r;
}

__device__ __forceinline__ void cp16(uint32_t saddr, const void* gptr, int bytes) {
    asm volatile("cp.async.cg.shared.global [%0], [%1], 16, %2;\n"
                 :: "r"(saddr), "l"(gptr), "r"(bytes));
}
__device__ __forceinline__ void cp_commit() { asm volatile("cp.async.commit_group;\n" ::: "memory"); }
__device__ __forceinline__ void cp_wait0()  { asm volatile("cp.async.wait_group 0;\n" ::: "memory"); }

#define MMA_TF32(d, a, b)                                                      \
    asm volatile(                                                              \
        "mma.sync.aligned.m16n8k8.row.col.f32.tf32.tf32.f32 "                  \
        "{%0,%1,%2,%3},{%4,%5,%6,%7},{%8,%9},{%0,%1,%2,%3};\n"                 \
        : "+f"(d[0]), "+f"(d[1]), "+f"(d[2]), "+f"(d[3])                       \
        : "r"(a[0]), "r"(a[1]), "r"(a[2]), "r"(a[3]), "r"(b[0]), "r"(b[1]))

// ---------------- tf32 tensor-core GEMM (cp.async double buffered) ---------
// C[M,N] = epilogue(A@B). A row-major MxK. B: KxN (transB=0) or NxK (transB=1).
// Batched via blockIdx.z with two-level strides. M%128==0, K%16==0, N%4==0.
// mode 0: C = alpha * acc
// mode 1: scores: C = (n<=m) ? acc*alpha*exp(p1[n]-p2[m]) : 0; fully-masked
//         tiles skipped; per-row sums atomically accumulated into p3.
// mode 2: row scale: C = acc * p1[m]; K limited to tileM+128 (A lower-tri).
#define BM 128
#define BN 128
#define BK 16
#define ASTR 20    // BK + 4 (conflict-free: g*20 mod 32 spans stride 4)
#define BSTR 132   // BN + 4

__global__ __launch_bounds__(256)
void tgemm_kernel(int M, int N, int K,
                  const float* __restrict__ A, int lda, long long sAb, long long sAn,
                  const float* __restrict__ B, int ldb, long long sBb, long long sBn,
                  float* __restrict__ C, int ldc, long long sCb, long long sCn,
                  int nhd, int transB, int mode, float alpha,
                  const float* __restrict__ p1, const float* __restrict__ p2,
                  float* __restrict__ p3, int pstr)
{
    const int z  = blockIdx.z;
    const int zb = z / nhd, zn = z % nhd;
    A += zb * sAb + zn * sAn;
    B += zb * sBb + zn * sBn;
    C += zb * sCb + zn * sCn;

    const int tileM = blockIdx.y * BM;
    const int tileN = blockIdx.x * BN;
    if (mode == 1 && tileN > tileM + BM - 1) return;   // fully masked tile

    const int t    = threadIdx.x;
    const int lane = t & 31;
    const int warp = t >> 5;
    const int g    = lane >> 2;     // 0..7
    const int t4   = lane & 3;      // 0..3
    const int wm   = (warp & 1) * 64;
    const int wn   = (warp >> 1) * 32;

    __shared__ float As[2][BM * ASTR];
    __shared__ float Bs[2][BM * ASTR];   // sized for max(NT: 128*20, NN: 16*132)

    float acc[4][4][4];
#pragma unroll
    for (int i = 0; i < 4; i++)
#pragma unroll
        for (int j = 0; j < 4; j++)
#pragma unroll
            for (int r = 0; r < 4; r++) acc[i][j][r] = 0.f;

    int Kend = K;
    if (mode == 2) { int lim = tileM + BM; Kend = lim < K ? lim : K; }
    const int nIter = Kend / BK;

    uint32_t sA[2], sB[2];
    sA[0] = (uint32_t)__cvta_generic_to_shared(&As[0][0]);
    sA[1] = (uint32_t)__cvta_generic_to_shared(&As[1][0]);
    sB[0] = (uint32_t)__cvta_generic_to_shared(&Bs[0][0]);
    sB[1] = (uint32_t)__cvta_generic_to_shared(&Bs[1][0]);

    // ---- async tile loaders ----
    auto loadTiles = [&](int stg, int k0) {
        // A: [BM][BK] K-contiguous chunks, 512 chunks / 256 threads
#pragma unroll
        for (int hh = 0; hh < 2; hh++) {
            int c   = t + hh * 256;
            int row = c >> 2;
            int kc  = (c & 3) * 4;
            const float* gp = &A[(long long)(tileM + row) * lda + k0 + kc];
            cp16(sA[stg] + (row * ASTR + kc) * 4, gp, 16);
        }
        if (!transB) {
#pragma unroll
            for (int hh = 0; hh < 2; hh++) {
                int c  = t + hh * 256;
                int kr = c >> 5;
                int n4 = (c & 31) * 4;
                int gn = tileN + n4;
                int ok = (gn < N);
                const float* gp = &B[(long long)(k0 + kr) * ldb + (ok ? gn : 0)];
                cp16(sB[stg] + (kr * BSTR + n4) * 4, gp, ok ? 16 : 0);
            }
        } else {
#pragma unroll
            for (int hh = 0; hh < 2; hh++) {
                int c   = t + hh * 256;
                int row = c >> 2;
                int kc  = (c & 3) * 4;
                const float* gp = &B[(long long)(tileN + row) * ldb + k0 + kc];
                cp16(sB[stg] + (row * ASTR + kc) * 4, gp, 16);
            }
        }
        cp_commit();
    };

    loadTiles(0, 0);
    cp_wait0();
    __syncthreads();

    for (int it = 0; it < nIter; it++) {
        const int s  = it & 1;
        const int kn = (it + 1) * BK;
        const bool more = (kn < Kend);
        if (more) loadTiles(s ^ 1, kn);

        const float* Asb = As[s];
        const float* Bsb = Bs[s];
#pragma unroll
        for (int ks = 0; ks < BK; ks += 8) {
            uint32_t af[4][4], bf[4][2];
#pragma unroll
            for (int i = 0; i < 4; i++) {
                int m0 = wm + i * 16 + g;
                af[i][0] = f2tf32(Asb[(m0    ) * ASTR + ks + t4    ]);
                af[i][1] = f2tf32(Asb[(m0 + 8) * ASTR + ks + t4    ]);
                af[i][2] = f2tf32(Asb[(m0    ) * ASTR + ks + t4 + 4]);
                af[i][3] = f2tf32(Asb[(m0 + 8) * ASTR + ks + t4 + 4]);
            }
#pragma unroll
            for (int j = 0; j < 4; j++) {
                int n0 = wn + j * 8 + g;
                if (transB) {
                    bf[j][0] = f2tf32(Bsb[n0 * ASTR + ks + t4    ]);
                    bf[j][1] = f2tf32(Bsb[n0 * ASTR + ks + t4 + 4]);
                } else {
                    bf[j][0] = f2tf32(Bsb[(ks + t4    ) * BSTR + n0]);
                    bf[j][1] = f2tf32(Bsb[(ks + t4 + 4) * BSTR + n0]);
                }
            }
#pragma unroll
            for (int i = 0; i < 4; i++)
#pragma unroll
                for (int j = 0; j < 4; j++)
                    MMA_TF32(acc[i][j], af[i], bf[j]);
        }

        if (more) cp_wait0();
        __syncthreads();
    }

    // ---- epilogue ----
    const long long zoff = (long long)z * pstr;
#pragma unroll
    for (int i = 0; i < 4; i++) {
        int gmBase = tileM + wm + i * 16 + g;
#pragma unroll
        for (int half = 0; half < 2; half++) {
            int gm = gmBase + half * 8;
            float pmv = 0.f, rsv = 1.f;
            if (mode == 1)      pmv = p2[zoff + gm];
            else if (mode == 2) rsv = p1[zoff + gm];
            float* Crow = C + (long long)gm * ldc;
            float rsum = 0.f;
#pragma unroll
            for (int j = 0; j < 4; j++) {
                int gn = tileN + wn + j * 8 + t4 * 2;
                if (gn >= N) continue;
                float v0 = acc[i][j][half * 2 + 0];
                float v1 = acc[i][j][half * 2 + 1];
                if (mode == 1) {
                    v0 = (gn     <= gm) ? v0 * alpha * __expf(p1[zoff + gn    ] - pmv) : 0.f;
                    v1 = (gn + 1 <= gm) ? v1 * alpha * __expf(p1[zoff + gn + 1] - pmv) : 0.f;
                    rsum += v0 + v1;
                } else if (mode == 2) {
                    v0 *= rsv; v1 *= rsv;
                } else {
                    v0 *= alpha; v1 *= alpha;
                }
                *reinterpret_cast<float2*>(&Crow[gn]) = make_float2(v0, v1);
            }
            if (mode == 1) {
                rsum += __shfl_xor_sync(0xffffffffu, rsum, 1);
                rsum += __shfl_xor_sync(0xffffffffu, rsum, 2);
                if (t4 == 0) atomicAdd(&p3[zoff + gm], rsum);
            }
        }
    }
}

// ---------------- depthwise causal conv + SiLU ----------------
__global__ void conv_silu_kernel(const float* __restrict__ xm,
                                 const float* __restrict__ w,
                                 const float* __restrict__ bias,
                                 float* __restrict__ xca)
{
    long long idx = (long long)blockIdx.x * blockDim.x + threadIdx.x;
    if (idx >= cBSH) return;
    int h = (int)(idx % cH);
    long long bs = idx / cH;
    int s = (int)(bs % cS);
    long long rowbase = (bs - s) * cH + h;
    float acc = bias[h];
#pragma unroll
    for (int tt = 0; tt < cKS; tt++) {
        int sp = s - (cKS - 1) + tt;
        if (sp >= 0) acc += xm[rowbase + (long long)sp * cH] * w[tt * cH + h];
    }
    float sg = 1.f / (1.f + __expf(-acc));
    xca[idx] = acc * sg;
}

// ---------------- headwise 4x4 projections (float4 weights) ----------------
__global__ void headwise_kernel(const float* __restrict__ xca,
                                const float* __restrict__ xm,
                                const float* __restrict__ Wq,
                                const float* __restrict__ Wk,
                                const float* __restrict__ Wv,
                                float* __restrict__ q,
                                float* __restrict__ k,
                                float* __restrict__ v)
{
    long long idx = (long long)blockIdx.x * blockDim.x + threadIdx.x;
    long long total = cBS * (long long)cNPH;
    if (idx >= total) return;
    int p = (int)(idx % cNPH);
    long long bs = idx / cNPH;
    long long base = bs * cH + p * 4;
    float4 xa = *reinterpret_cast<const float4*>(xca + base);
    float4 xv = *reinterpret_cast<const float4*>(xm + base);
    const float4* wq4 = reinterpret_cast<const float4*>(Wq + p * 16);
    const float4* wk4 = reinterpret_cast<const float4*>(Wk + p * 16);
    const float4* wv4 = reinterpret_cast<const float4*>(Wv + p * 16);
    float4 q0 = wq4[0], q1 = wq4[1], q2 = wq4[2], q3 = wq4[3];
    float4 k0 = wk4[0], k1 = wk4[1], k2 = wk4[2], k3 = wk4[3];
    float4 v0 = wv4[0], v1 = wv4[1], v2 = wv4[2], v3 = wv4[3];
    float4 qo, ko, vo;
    qo.x = xa.x*q0.x + xa.y*q1.x + xa.z*q2.x + xa.w*q3.x;
    qo.y = xa.x*q0.y + xa.y*q1.y + xa.z*q2.y + xa.w*q3.y;
    qo.z = xa.x*q0.z + xa.y*q1.z + xa.z*q2.z + xa.w*q3.z;
    qo.w = xa.x*q0.w + xa.y*q1.w + xa.z*q2.w + xa.w*q3.w;
    ko.x = xa.x*k0.x + xa.y*k1.x + xa.z*k2.x + xa.w*k3.x;
    ko.y = xa.x*k0.y + xa.y*k1.y + xa.z*k2.y + xa.w*k3.y;
    ko.z = xa.x*k0.z + xa.y*k1.z + xa.z*k2.z + xa.w*k3.z;
    ko.w = xa.x*k0.w + xa.y*k1.w + xa.z*k2.w + xa.w*k3.w;
    vo.x = xv.x*v0.x + xv.y*v1.x + xv.z*v2.x + xv.w*v3.x;
    vo.y = xv.x*v0.y + xv.y*v1.y + xv.z*v2.y + xv.w*v3.y;
    vo.z = xv.x*v0.z + xv.y*v1.z + xv.z*v2.z + xv.w*v3.z;
    vo.w = xv.x*v0.w + xv.y*v1.w + xv.z*v2.w + xv.w*v3.w;
    *reinterpret_cast<float4*>(q + base) = qo;
    *reinterpret_cast<float4*>(k + base) = ko;
    *reinterpret_cast<float4*>(v + base) = vo;
}

// ---------------- gate projections (4 rows / block) ----------------
#define GROWS 4
__global__ __launch_bounds__(256)
void gates_kernel(const float* __restrict__ q, const float* __restrict__ k,
                  const float* __restrict__ v,
                  const float* __restrict__ Wig, const float* __restrict__ big,
                  const float* __restrict__ Wfg, const float* __restrict__ bfg,
                  float* __restrict__ ipre, float* __restrict__ fpre)
{
    int bs0 = blockIdx.x * GROWS;
    int t   = threadIdx.x;
    float ai[GROWS][4], afr[GROWS][4];
#pragma unroll
    for (int rw = 0; rw < GROWS; rw++)
#pragma unroll
        for (int n = 0; n < 4; n++) { ai[rw][n] = 0.f; afr[rw][n] = 0.f; }

    for (int r = t; r < 3 * cH; r += 256) {
        float4 wi = *reinterpret_cast<const float4*>(Wig + (long long)r * 4);
        float4 wf = *reinterpret_cast<const float4*>(Wfg + (long long)r * 4);
        const float* src;
        int col;
        if (r < cH)          { src = q; col = r; }
        else if (r < 2 * cH) { src = k; col = r - cH; }
        else                 { src = v; col = r - 2 * cH; }
#pragma unroll
        for (int rw = 0; rw < GROWS; rw++) {
            float val = src[(long long)(bs0 + rw) * cH + col];
            ai[rw][0] += val * wi.x; ai[rw][1] += val * wi.y;
            ai[rw][2] += val * wi.z; ai[rw][3] += val * wi.w;
            afr[rw][0] += val * wf.x; afr[rw][1] += val * wf.y;
            afr[rw][2] += val * wf.z; afr[rw][3] += val * wf.w;
        }
    }

    __shared__ float red[8][256];
    for (int rw = 0; rw < GROWS; rw++) {
#pragma unroll
        for (int n = 0; n < 4; n++) { red[n][t] = ai[rw][n]; red[4 + n][t] = afr[rw][n]; }
        __syncthreads();
        for (int o = 128; o > 0; o >>= 1) {
            if (t < o) {
#pragma unroll
                for (int m = 0; m < 8; m++) red[m][t] += red[m][t + o];
            }
            __syncthreads();
        }
        if (t == 0) {
            int bs = bs0 + rw;
            int b = bs / cS, s = bs % cS;
#pragma unroll
            for (int n = 0; n < 4; n++) {
                ipre[(long long)(b * cNH + n) * cS + s] = red[n][0] + big[n];
                fpre[(long long)(b * cNH + n) * cS + s] = red[4 + n][0] + bfg[n];
            }
        }
        __syncthreads();
    }
}

// ---------------- scan: cumsum(logsigmoid(f)), a = i - cs, prefix-max(a) ----
__global__ __launch_bounds__(256)
void scan_kernel(const float* __restrict__ ipre, const float* __restrict__ fpre,
                 float* __restrict__ cs, float* __restrict__ aArr,
                 float* __restrict__ pm, float* __restrict__ nsum)
{
    int bh = blockIdx.x;
    int t  = threadIdx.x;
    const float* fp = fpre + (long long)bh * cS;
    const float* ip = ipre + (long long)bh * cS;

    float loc[8];
    float sum = 0.f;
#pragma unroll
    for (int u = 0; u < 8; u++) {
        int j = t * 8 + u;
        float f = fp[j];
        float lf = fminf(f, 0.f) - log1pf(expf(-fabsf(f)));
        sum += lf;
        loc[u] = sum;
    }
    __shared__ float part[256];
    part[t] = sum;
    __syncthreads();
    for (int off = 1; off < 256; off <<= 1) {
        float vv = (t >= off) ? part[t - off] : 0.f;
        __syncthreads();
        part[t] += vv;
        __syncthreads();
    }
    float excl = part[t] - sum;

    float lmax[8];
    float amax = -1e30f;
#pragma unroll
    for (int u = 0; u < 8; u++) {
        int j = t * 8 + u;
        float csj = excl + loc[u];
        cs[(long long)bh * cS + j] = csj;
        float aj = ip[j] - csj;
        aArr[(long long)bh * cS + j] = aj;
        nsum[(long long)bh * cS + j] = 0.f;
        amax = fmaxf(amax, aj);
        lmax[u] = amax;
    }
    __syncthreads();
    part[t] = amax;
    __syncthreads();
    for (int off = 1; off < 256; off <<= 1) {
        float vv = (t >= off) ? part[t - off] : -1e30f;
        __syncthreads();
        part[t] = fmaxf(part[t], vv);
        __syncthreads();
    }
    float exmax = (t > 0) ? part[t - 1] : -1e30f;
#pragma unroll
    for (int u = 0; u < 8; u++) {
        int j = t * 8 + u;
        pm[(long long)bh * cS + j] = fmaxf(exmax, lmax[u]);
    }
}

// ---------------- finalize n -> rs ----------------
__global__ void nfin_kernel(const float* __restrict__ nsum,
                            const float* __restrict__ cs, const float* __restrict__ pm,
                            float* __restrict__ rs)
{
    int idx = blockIdx.x * blockDim.x + threadIdx.x;
    if (idx >= cBHS) return;
    float m = cs[idx] + pm[idx];
    float n = fmaxf(fabsf(nsum[idx]), __expf(-m));
    rs[idx] = 1.f / (n + 1e-6f);
}

// ---------------- multi-head LN + skip + z-gate ----------------
__global__ __launch_bounds__(256)
void ln_kernel(const float* __restrict__ hbuf, const float* __restrict__ xca,
               const float* __restrict__ zbuf, const float* __restrict__ norm_w,
               const float* __restrict__ skip, float* __restrict__ hs)
{
    int s  = blockIdx.x;
    int bh = blockIdx.y;
    int t  = threadIdx.x;
    int b = bh / cNH, n = bh % cNH;
    const float* hrow = hbuf + ((long long)bh * cS + s) * cDH;

    float sum = 0.f, ss = 0.f;
    for (int d = t; d < cDH; d += 256) {
        float v = hrow[d];
        sum += v; ss += v * v;
    }
    __shared__ float r1[256], r2[256];
    r1[t] = sum; r2[t] = ss;
    __syncthreads();
    for (int o = 128; o > 0; o >>= 1) {
        if (t < o) { r1[t] += r1[t + o]; r2[t] += r2[t + o]; }
        __syncthreads();
    }
    float mean = r1[0] / cDH;
    float var  = r2[0] / cDH - mean * mean;
    float inv  = rsqrtf(var + 1e-5f);

    long long xbase = ((long long)b * cS + s) * cH;
    for (int d = t; d < cDH; d += 256) {
        int col = n * cDH + d;
        float hn = (hrow[d] - mean) * inv * norm_w[col];
        float hk = hn + skip[col] * xca[xbase + col];
        float zv = zbuf[xbase + col];
        float sz = zv / (1.f + __expf(-zv));
        hs[xbase + col] = hk * sz;
    }
}

// ---------------- launch ----------------
extern "C" void kernel_launch(void* const* d_in, const int* in_sizes, int n_in,
                              void* d_out, int out_size)
{
    const float* x      = (const float*)d_in[0];
    const float* W_in   = (const float*)d_in[1];
    const float* conv_w = (const float*)d_in[2];
    const float* conv_b = (const float*)d_in[3];
    const float* Wq     = (const float*)d_in[4];
    const float* Wk     = (const float*)d_in[5];
    const float* Wv     = (const float*)d_in[6];
    const float* W_ig   = (const float*)d_in[7];
    const float* b_ig   = (const float*)d_in[8];
    const float* W_fg   = (const float*)d_in[9];
    const float* b_fg   = (const float*)d_in[10];
    const float* norm_w = (const float*)d_in[11];
    const float* skip   = (const float*)d_in[12];
    const float* W_out  = (const float*)d_in[13];
    float* out = (float*)d_out;

    float *p_xm, *p_z, *p_xca, *p_q, *p_k, *p_v, *p_h, *p_hs, *p_sc;
    float *p_ipre, *p_fpre, *p_cs, *p_a, *p_pm, *p_rs, *p_ns;
    cudaGetSymbolAddress((void**)&p_xm,  g_xm);
    cudaGetSymbolAddress((void**)&p_z,   g_z);
    cudaGetSymbolAddress((void**)&p_xca, g_xca);
    cudaGetSymbolAddress((void**)&p_q,   g_q);
    cudaGetSymbolAddress((void**)&p_k,   g_k);
    cudaGetSymbolAddress((void**)&p_v,   g_v);
    cudaGetSymbolAddress((void**)&p_h,   g_h);
    cudaGetSymbolAddress((void**)&p_hs,  g_hs);
    cudaGetSymbolAddress((void**)&p_sc,  g_scores);
    cudaGetSymbolAddress((void**)&p_ipre, g_ipre);
    cudaGetSymbolAddress((void**)&p_fpre, g_fpre);
    cudaGetSymbolAddress((void**)&p_cs,  g_cs);
    cudaGetSymbolAddress((void**)&p_a,   g_a);
    cudaGetSymbolAddress((void**)&p_pm,  g_pm);
    cudaGetSymbolAddress((void**)&p_rs,  g_rs);
    cudaGetSymbolAddress((void**)&p_ns,  g_nsum);

    const int M0 = (int)cBS;  // 4096

    // 1) x @ W_in[:, :H] -> xm ; x @ W_in[:, H:] -> z
    {
        dim3 grid(cH / BN, M0 / BM, 1);
        tgemm_kernel<<<grid, 256>>>(M0, cH, cE,
            x, cE, 0, 0,
            W_in, 2 * cH, 0, 0,
            p_xm, cH, 0, 0,
            1, 0, 0, 1.0f, nullptr, nullptr, nullptr, 0);
        tgemm_kernel<<<grid, 256>>>(M0, cH, cE,
            x, cE, 0, 0,
            W_in + cH, 2 * cH, 0, 0,
            p_z, cH, 0, 0,
            1, 0, 0, 1.0f, nullptr, nullptr, nullptr, 0);
    }

    // 2) depthwise causal conv + SiLU
    {
        long long total = cBSH;
        int blocks = (int)((total + 255) / 256);
        conv_silu_kernel<<<blocks, 256>>>(p_xm, conv_w, conv_b, p_xca);
    }

    // 3) headwise q/k/v
    {
        long long total = cBS * (long long)cNPH;
        int blocks = (int)((total + 255) / 256);
        headwise_kernel<<<blocks, 256>>>(p_xca, p_xm, Wq, Wk, Wv, p_q, p_k, p_v);
    }

    // 4) gates
    gates_kernel<<<M0 / GROWS, 256>>>(p_q, p_k, p_v, W_ig, b_ig, W_fg, b_fg, p_ipre, p_fpre);

    // 5) scan (also zeroes nsum)
    scan_kernel<<<cB * cNH, 256>>>(p_ipre, p_fpre, p_cs, p_a, p_pm, p_ns);

    // 6) scores = (q k^T / sqrt(DH)) * exp(a_j - pm_i), causal, + fused row sums
    {
        dim3 grid(cS / BN, cS / BM, cB * cNH);
        float alpha = 1.0f / sqrtf((float)cDH);
        tgemm_kernel<<<grid, 256>>>(cS, cS, cDH,
            p_q, cH, (long long)cS * cH, (long long)cDH,
            p_k, cH, (long long)cS * cH, (long long)cDH,
            p_sc, cS, (long long)cNH * cS * cS, (long long)cS * cS,
            cNH, 1, 1, alpha, p_a, p_pm, p_ns, cS);
    }

    // 7) finalize rs
    nfin_kernel<<<(cBHS + 255) / 256, 256>>>(p_ns, p_cs, p_pm, p_rs);

    // 8) h = diag(rs) * scores @ v   (causal K-limit)
    {
        dim3 grid((cDH + BN - 1) / BN, cS / BM, cB * cNH);
        tgemm_kernel<<<grid, 256>>>(cS, cDH, cS,
            p_sc, cS, (long long)cNH * cS * cS, (long long)cS * cS,
            p_v, cH, (long long)cS * cH, (long long)cDH,
            p_h, cDH, (long long)cNH * cS * cDH, (long long)cS * cDH,
            cNH, 0, 2, 1.0f, p_rs, nullptr, nullptr, cS);
    }

    // 9) LN + skip + z gate
    {
        dim3 grid(cS, cB * cNH);
        ln_kernel<<<grid, 256>>>(p_h, p_xca, p_z, norm_w, skip, p_hs);
    }

    // 10) out = hs @ W_out
    {
        dim3 grid(cE / BN, M0 / BM, 1);
        tgemm_kernel<<<grid, 256>>>(M0, cE, cH,
            p_hs, cH, 0, 0,
            W_out, cE, 0, 0,
            out, cE, 0, 0,
            1, 0, 0, 1.0f, nullptr, nullptr, nullptr, 0);
    }
}